// round 3
// baseline (speedup 1.0000x reference)
#include <cuda_runtime.h>
#include <cstddef>

// ---------------------------------------------------------------------------
// SLAYER SRM-alpha SNN — R1 numerics (bit-identical op order), fused structure:
//   scan(psp) -> conv1 -> [spike+psp + pool + spike+psp] -> conv2 ->
//   [spike+psp + pool + spike+psp] -> conv3 -> [spike+psp] -> dense -> [spike]
// Layout: [N,C,H,W,T], T innermost, T=300, N=8.
// ---------------------------------------------------------------------------

#define T_LEN  300
#define TC4    75
#define NBATCH 8

typedef unsigned long long ull;

#define C_DS 0.90483741803595952f     // exp(-1/10)
#define C_B  0.27182818284590452f     // e/10
#define C_DR 0.36787944117144233f     // exp(-1)
#define C_A  (-54.365636569180902f)   // -2*10*e
#define C_TH 10.0f
#define C_POOL 11.0f

#define BUF_ELEMS 30105600
__device__ float g_bufA[BUF_ELEMS + 16];
__device__ float g_bufB[BUF_ELEMS + 16];

__device__ __forceinline__ ull ffma2(ull a, ull b, ull c) {
    ull d;
    asm("fma.rn.f32x2 %0, %1, %2, %3;" : "=l"(d) : "l"(a), "l"(b), "l"(c));
    return d;
}

// ---------------------------------------------------------------------------
// Temporal scan (R1-identical arithmetic). MODE: 0 = psp only,
// 1 = spike then psp, 2 = spike only. f32 in/out.
// ---------------------------------------------------------------------------
template<int MODE>
__global__ __launch_bounds__(128)
void scan_ps(const float* __restrict__ x, float* __restrict__ y,
             int numNeurons) {
    __shared__ float tile[128][33];
    const int tid = threadIdx.x, lane = tid & 31, warp = tid >> 5;
    const int nb  = blockIdx.x * 128;
    const bool act = (nb + tid) < numNeurons;

    float p_r = 0.f, q_r = 0.f, p_s = 0.f, q_s = 0.f;

    for (int tb = 0; tb < T_LEN; tb += 32) {
        const int cl = min(32, T_LEN - tb);
        #pragma unroll 8
        for (int k = 0; k < 32; k++) {
            int nrn = k * 4 + warp, gn = nb + nrn;
            if (gn < numNeurons && lane < cl)
                tile[nrn][lane] = x[(size_t)gn * T_LEN + tb + lane];
        }
        __syncthreads();
        if (act) {
            for (int k = 0; k < cl; k++) {
                float u = tile[tid][k];
                float outv;
                if (MODE == 0) {
                    q_s = C_DS * (q_s + p_s);
                    p_s = C_DS * p_s + u;
                    outv = C_B * q_s;
                } else {
                    q_r = C_DR * (q_r + p_r);
                    float v = u + C_A * q_r;
                    float s = (v >= C_TH) ? 1.0f : 0.0f;
                    p_r = C_DR * p_r + s;
                    if (MODE == 1) {
                        q_s = C_DS * (q_s + p_s);
                        p_s = C_DS * p_s + s;
                        outv = C_B * q_s;
                    } else {
                        outv = s;
                    }
                }
                tile[tid][k] = outv;
            }
        }
        __syncthreads();
        #pragma unroll 8
        for (int k = 0; k < 32; k++) {
            int nrn = k * 4 + warp, gn = nb + nrn;
            if (gn < numNeurons && lane < cl)
                y[(size_t)gn * T_LEN + tb + lane] = tile[nrn][lane];
        }
        __syncthreads();
    }
}

// ---------------------------------------------------------------------------
// Fused: per 2x2 group, run [spike+psp] on 4 children (from conv output u),
// pool their psp values (*11, R1 sum order), then [spike+psp] on the pooled
// drive. One thread per pooled neuron; 5 recurrences in registers.
// Bit-identical to R1's scan_ps<1> + pool_kernel + scan_ps<1>.
// ---------------------------------------------------------------------------
#define PTILE 16
__global__ __launch_bounds__(128)
void scanpool2x(const float* __restrict__ x, float* __restrict__ y,
                int C, int OH, int OW) {
    __shared__ float tile[128][85];   // [thr][ch*17 + t] children, [68+t] out
    __shared__ int rb[128][4];
    const int tid = threadIdx.x, lane = tid & 31, warp = tid >> 5;
    const int gn  = blockIdx.x * 128 + tid;   // pooled neuron (grid exact)
    {
        int ox = gn % OW; int r = gn / OW;
        int oy = r % OH;  r /= OH;
        int c  = r % C;   int n = r / C;
        const int W = OW * 2, H = OH * 2;
        int base = (((n * C + c) * H + 2 * oy) * W + 2 * ox) * T_LEN;
        rb[tid][0] = base;
        rb[tid][1] = base + T_LEN;
        rb[tid][2] = base + W * T_LEN;
        rb[tid][3] = base + (W + 1) * T_LEN;
    }
    __syncthreads();

    float cpr[4] = {0,0,0,0}, cqr[4] = {0,0,0,0};
    float cps[4] = {0,0,0,0}, cqs[4] = {0,0,0,0};
    float Ppr = 0.f, Pqr = 0.f, Pps = 0.f, Pqs = 0.f;

    for (int tb = 0; tb < T_LEN; tb += PTILE) {
        const int cl = min(PTILE, T_LEN - tb);
        // load 512 child rows (cl t's each); 2 rows per warp-iter
        #pragma unroll 8
        for (int it = 0; it < 64; it++) {
            int row = it * 8 + warp * 2 + (lane >> 4);  // 0..511
            int t   = lane & 15;
            int thr = row >> 2, ch = row & 3;
            if (t < cl)
                tile[thr][ch * 17 + t] = x[rb[thr][ch] + tb + t];
        }
        __syncthreads();
        for (int k = 0; k < cl; k++) {
            float outc[4];
            #pragma unroll
            for (int c = 0; c < 4; c++) {
                float u = tile[tid][c * 17 + k];
                cqr[c] = C_DR * (cqr[c] + cpr[c]);
                float v = u + C_A * cqr[c];
                float s = (v >= C_TH) ? 1.0f : 0.0f;
                cpr[c] = C_DR * cpr[c] + s;
                cqs[c] = C_DS * (cqs[c] + cps[c]);
                cps[c] = C_DS * cps[c] + s;
                outc[c] = C_B * cqs[c];
            }
            float U = (outc[0] + outc[1] + outc[2] + outc[3]) * C_POOL;
            Pqr = C_DR * (Pqr + Ppr);
            float v = U + C_A * Pqr;
            float s = (v >= C_TH) ? 1.0f : 0.0f;
            Ppr = C_DR * Ppr + s;
            Pqs = C_DS * (Pqs + Pps);
            Pps = C_DS * Pps + s;
            tile[tid][68 + k] = C_B * Pqs;
        }
        __syncthreads();
        // store 128 pooled rows
        #pragma unroll 4
        for (int it = 0; it < 16; it++) {
            int row = it * 8 + warp * 2 + (lane >> 4);
            int t   = lane & 15;
            if (t < cl)
                y[(size_t)(blockIdx.x * 128 + row) * T_LEN + tb + t]
                    = tile[row][68 + t];
        }
        __syncthreads();
    }
}

// ---------------------------------------------------------------------------
// Direct conv, f32 input, float4 over t, CO_BLK=16 output channels/thread.
// Weights in smem transposed [tap][o] (duplicated float2) -> LDS.128 pairs.
// Accumulation order per output identical to R1 (ci,kh,kw sequence).
// ---------------------------------------------------------------------------
template<int CI, int CO, int CO_BLK, int K, int H, int W, int OH, int OW, int PAD>
__global__ __launch_bounds__(256)
void conv_kernel(const float* __restrict__ x, const float* __restrict__ wgt,
                 float* __restrict__ y) {
    constexpr int TAPS = CI * K * K;
    __shared__ float2 ws[TAPS * CO_BLK];
    const int oBase = blockIdx.y * CO_BLK;
    for (int i = threadIdx.x; i < TAPS * CO_BLK; i += blockDim.x) {
        int o = i % CO_BLK, tap = i / CO_BLK;
        float v = wgt[(oBase + o) * TAPS + tap];
        ws[i] = make_float2(v, v);
    }
    __syncthreads();

    long long g = (long long)blockIdx.x * blockDim.x + threadIdx.x;
    int tc = (int)(g % TC4); long long r = g / TC4;
    int ox = (int)(r % OW); r /= OW;
    int oy = (int)(r % OH); r /= OH;
    int n  = (int)r;
    if (n >= NBATCH) return;

    ulonglong2 acc[CO_BLK];
    #pragma unroll
    for (int o = 0; o < CO_BLK; o++) acc[o] = make_ulonglong2(0ULL, 0ULL);

    const float* xb = x + (size_t)n * CI * H * W * T_LEN + tc * 4;

    #pragma unroll 1
    for (int ci = 0; ci < CI; ci++) {
        #pragma unroll
        for (int kh = 0; kh < K; kh++) {
            int iy = oy + kh - PAD;
            if ((unsigned)iy >= (unsigned)H) continue;
            const float* xrow = xb + (size_t)(ci * H + iy) * W * T_LEN;
            #pragma unroll
            for (int kw = 0; kw < K; kw++) {
                int ix = ox + kw - PAD;
                if ((unsigned)ix >= (unsigned)W) continue;
                float4 f = *(const float4*)(xrow + (size_t)ix * T_LEN);
                ulonglong2 xu = *(ulonglong2*)&f;
                const float2* wrow = &ws[((ci * K + kh) * K + kw) * CO_BLK];
                #pragma unroll
                for (int o = 0; o < CO_BLK; o += 2) {
                    float4 wv = *(const float4*)(wrow + o);
                    ull w0 = ((ull*)&wv)[0];
                    ull w1 = ((ull*)&wv)[1];
                    acc[o].x   = ffma2(w0, xu.x, acc[o].x);
                    acc[o].y   = ffma2(w0, xu.y, acc[o].y);
                    acc[o+1].x = ffma2(w1, xu.x, acc[o+1].x);
                    acc[o+1].y = ffma2(w1, xu.y, acc[o+1].y);
                }
            }
        }
    }
    #pragma unroll
    for (int o = 0; o < CO_BLK; o++) {
        size_t off = (((size_t)(n * CO + oBase + o) * OH + oy) * OW + ox) * T_LEN
                     + tc * 4;
        *(ulonglong2*)(y + off) = acc[o];
    }
}

// ---------------------------------------------------------------------------
// Dense over (C,H,W)=3136 per timestep: x [8,64,7,7,300] f32 -> [8,10,300].
// ---------------------------------------------------------------------------
__global__ __launch_bounds__(256)
void dense_kernel(const float* __restrict__ x, const float* __restrict__ wgt,
                  float* __restrict__ y) {
    int g = blockIdx.x * blockDim.x + threadIdx.x;
    if (g >= NBATCH * 10 * T_LEN) return;
    int t = g % T_LEN; int r = g / T_LEN;
    int o = r % 10;    int n = r / 10;
    const float* xb = x + (size_t)n * 3136 * T_LEN + t;
    const float* wb = wgt + o * 3136;
    float acc = 0.f;
    #pragma unroll 8
    for (int i = 0; i < 3136; i++)
        acc = fmaf(wb[i], xb[(size_t)i * T_LEN], acc);
    y[g] = acc;
}

// ---------------------------------------------------------------------------

static inline int cdiv(long long a, long long b) { return (int)((a + b - 1) / b); }

extern "C" void kernel_launch(void* const* d_in, const int* in_sizes, int n_in,
                              void* d_out, int out_size) {
    const float* in = (const float*)d_in[0];   // [8,1,30,30,300]
    const float* w1 = (const float*)d_in[1];   // [16,1,5,5]
    const float* w2 = (const float*)d_in[2];   // [32,16,3,3]
    const float* w3 = (const float*)d_in[3];   // [64,32,3,3]
    const float* w4 = (const float*)d_in[4];   // [10,64,7,7]
    float* out = (float*)d_out;                // [8,10,300]

    float *bufA, *bufB;
    cudaGetSymbolAddress((void**)&bufA, g_bufA);
    cudaGetSymbolAddress((void**)&bufB, g_bufB);

    // P0 = psp(input)  [8,1,30,30,300]
    scan_ps<0><<<cdiv(7200, 128), 128>>>(in, bufA, 7200);

    // u1 = conv1(P0)   [8,16,28,28,300]
    conv_kernel<1, 16, 16, 5, 30, 30, 28, 28, 1>
        <<<dim3(cdiv((long long)NBATCH * 28 * 28 * TC4, 256), 1), 256>>>(bufA, w1, bufB);

    // Q2 = psp(spike(pool(psp(spike(u1)))))  [8,16,14,14,300]
    scanpool2x<<<25088 / 128, 128>>>(bufB, bufA, 16, 14, 14);

    // u3 = conv2(Q2)   [8,32,14,14,300]
    conv_kernel<16, 32, 16, 3, 14, 14, 14, 14, 1>
        <<<dim3(cdiv((long long)NBATCH * 14 * 14 * TC4, 256), 2), 256>>>(bufA, w2, bufB);

    // Q4 = psp(spike(pool(psp(spike(u3)))))  [8,32,7,7,300]
    scanpool2x<<<12544 / 128, 128>>>(bufB, bufA, 32, 7, 7);

    // u5 = conv3(Q4)   [8,64,7,7,300]
    conv_kernel<32, 64, 16, 3, 7, 7, 7, 7, 1>
        <<<dim3(cdiv((long long)NBATCH * 7 * 7 * TC4, 256), 4), 256>>>(bufA, w3, bufB);

    // Q5 = psp(spike(u5))  [8,64,7,7,300]
    scan_ps<1><<<cdiv(25088, 128), 128>>>(bufB, bufA, 25088);

    // u6 = dense(Q5)   [8,10,300]
    dense_kernel<<<cdiv(NBATCH * 10 * T_LEN, 256), 256>>>(bufA, w4, bufB);

    // out = spike(u6)
    scan_ps<2><<<1, 128>>>(bufB, out, 80);
}

// round 4
// speedup vs baseline: 2.4369x; 2.4369x over previous
#include <cuda_runtime.h>
#include <cstddef>

// ---------------------------------------------------------------------------
// SLAYER SRM-alpha SNN — R1/R3 bit-identical arithmetic, rebuilt data movement:
// scans are smem-free (thread-owned rows, float4 quads, full-sector loads),
// conv uses CO_BLK=8 for occupancy. Layout [N,C,H,W,T], T innermost, T=300.
// ---------------------------------------------------------------------------

#define T_LEN  300
#define TC4    75
#define NBATCH 8

typedef unsigned long long ull;

#define C_DS 0.90483741803595952f     // exp(-1/10)
#define C_B  0.27182818284590452f     // e/10
#define C_DR 0.36787944117144233f     // exp(-1)
#define C_A  (-54.365636569180902f)   // -2*10*e
#define C_TH 10.0f
#define C_POOL 11.0f

#define BUF_ELEMS 30105600
__device__ float g_bufA[BUF_ELEMS + 16];
__device__ float g_bufB[BUF_ELEMS + 16];

__device__ __forceinline__ ull ffma2(ull a, ull b, ull c) {
    ull d;
    asm("fma.rn.f32x2 %0, %1, %2, %3;" : "=l"(d) : "l"(a), "l"(b), "l"(c));
    return d;
}

// element k (0..15) of a float4[ ] quad array; folds under full unroll
#define ELT(v, k) (((k) & 3) == 0 ? (v)[(k) >> 2].x : \
                   ((k) & 3) == 1 ? (v)[(k) >> 2].y : \
                   ((k) & 3) == 2 ? (v)[(k) >> 2].z : (v)[(k) >> 2].w)

// ---------------------------------------------------------------------------
// Temporal scan, smem-free. MODE: 0=psp, 1=spike+psp, 2=spike.
// ---------------------------------------------------------------------------
template<int CL, int MODE>
__device__ __forceinline__ void scan_tile(const float* __restrict__ xr,
                                          float* __restrict__ yr,
                                          float& p_s, float& q_s,
                                          float& p_r, float& q_r) {
    constexpr int NQ = CL / 4;
    float4 v[NQ];
    #pragma unroll
    for (int q = 0; q < NQ; q++) v[q] = *(const float4*)(xr + q * 4);
    float o[CL];
    #pragma unroll
    for (int k = 0; k < CL; k++) {
        float u = ELT(v, k);
        if (MODE == 0) {
            q_s = C_DS * (q_s + p_s);
            p_s = C_DS * p_s + u;
            o[k] = C_B * q_s;
        } else {
            q_r = C_DR * (q_r + p_r);
            float vm = u + C_A * q_r;
            float s = (vm >= C_TH) ? 1.0f : 0.0f;
            p_r = C_DR * p_r + s;
            if (MODE == 1) {
                q_s = C_DS * (q_s + p_s);
                p_s = C_DS * p_s + s;
                o[k] = C_B * q_s;
            } else {
                o[k] = s;
            }
        }
    }
    #pragma unroll
    for (int q = 0; q < NQ; q++)
        *(float4*)(yr + q * 4) =
            make_float4(o[q * 4], o[q * 4 + 1], o[q * 4 + 2], o[q * 4 + 3]);
}

template<int MODE>
__global__ __launch_bounds__(128)
void scan_t(const float* __restrict__ x, float* __restrict__ y,
            int numNeurons) {
    int gn = blockIdx.x * 128 + threadIdx.x;
    if (gn >= numNeurons) return;
    const float* xr = x + (size_t)gn * T_LEN;
    float*       yr = y + (size_t)gn * T_LEN;
    float p_s = 0.f, q_s = 0.f, p_r = 0.f, q_r = 0.f;
    #pragma unroll 1
    for (int tb = 0; tb < 288; tb += 16)
        scan_tile<16, MODE>(xr + tb, yr + tb, p_s, q_s, p_r, q_r);
    scan_tile<12, MODE>(xr + 288, yr + 288, p_s, q_s, p_r, q_r);   // 300=18*16+12
}

// ---------------------------------------------------------------------------
// Fused [spike+psp on 4 children] + 2x2 pool(*11) + [spike+psp], smem-free.
// One thread per pooled neuron; bit-identical to R1's scan+pool+scan chain.
// ---------------------------------------------------------------------------
template<int CL>
__device__ __forceinline__ void pool_tile(
    const float* __restrict__ x0, const float* __restrict__ x1,
    const float* __restrict__ x2, const float* __restrict__ x3,
    float* __restrict__ yr,
    float* cpr, float* cqr, float* cps, float* cqs,
    float& Ppr, float& Pqr, float& Pps, float& Pqs) {
    constexpr int NQ = CL / 4;
    float4 v0[NQ], v1[NQ], v2[NQ], v3[NQ];
    #pragma unroll
    for (int q = 0; q < NQ; q++) v0[q] = *(const float4*)(x0 + q * 4);
    #pragma unroll
    for (int q = 0; q < NQ; q++) v1[q] = *(const float4*)(x1 + q * 4);
    #pragma unroll
    for (int q = 0; q < NQ; q++) v2[q] = *(const float4*)(x2 + q * 4);
    #pragma unroll
    for (int q = 0; q < NQ; q++) v3[q] = *(const float4*)(x3 + q * 4);
    float o[CL];
    #pragma unroll
    for (int k = 0; k < CL; k++) {
        float outc[4];
        #pragma unroll
        for (int c = 0; c < 4; c++) {
            float u = (c == 0) ? ELT(v0, k) : (c == 1) ? ELT(v1, k)
                    : (c == 2) ? ELT(v2, k) : ELT(v3, k);
            cqr[c] = C_DR * (cqr[c] + cpr[c]);
            float vm = u + C_A * cqr[c];
            float s  = (vm >= C_TH) ? 1.0f : 0.0f;
            cpr[c] = C_DR * cpr[c] + s;
            cqs[c] = C_DS * (cqs[c] + cps[c]);
            cps[c] = C_DS * cps[c] + s;
            outc[c] = C_B * cqs[c];
        }
        float U = (outc[0] + outc[1] + outc[2] + outc[3]) * C_POOL;
        Pqr = C_DR * (Pqr + Ppr);
        float vm = U + C_A * Pqr;
        float s  = (vm >= C_TH) ? 1.0f : 0.0f;
        Ppr = C_DR * Ppr + s;
        Pqs = C_DS * (Pqs + Pps);
        Pps = C_DS * Pps + s;
        o[k] = C_B * Pqs;
    }
    #pragma unroll
    for (int q = 0; q < NQ; q++)
        *(float4*)(yr + q * 4) =
            make_float4(o[q * 4], o[q * 4 + 1], o[q * 4 + 2], o[q * 4 + 3]);
}

__global__ __launch_bounds__(128)
void scanpool2x(const float* __restrict__ x, float* __restrict__ y,
                int C, int OH, int OW) {
    const int gn = blockIdx.x * 128 + threadIdx.x;  // grid exact
    int ox = gn % OW; int r = gn / OW;
    int oy = r % OH;  r /= OH;
    int c  = r % C;   int n = r / C;
    const int W = OW * 2, H = OH * 2;
    size_t base = (((size_t)(n * C + c) * H + 2 * oy) * W + 2 * ox) * T_LEN;
    const float* x0 = x + base;
    const float* x1 = x + base + T_LEN;
    const float* x2 = x + base + (size_t)W * T_LEN;
    const float* x3 = x + base + (size_t)(W + 1) * T_LEN;
    float* yr = y + (size_t)gn * T_LEN;

    float cpr[4] = {0,0,0,0}, cqr[4] = {0,0,0,0};
    float cps[4] = {0,0,0,0}, cqs[4] = {0,0,0,0};
    float Ppr = 0.f, Pqr = 0.f, Pps = 0.f, Pqs = 0.f;

    #pragma unroll 1
    for (int tb = 0; tb < 288; tb += 16)
        pool_tile<16>(x0 + tb, x1 + tb, x2 + tb, x3 + tb, yr + tb,
                      cpr, cqr, cps, cqs, Ppr, Pqr, Pps, Pqs);
    pool_tile<12>(x0 + 288, x1 + 288, x2 + 288, x3 + 288, yr + 288,
                  cpr, cqr, cps, cqs, Ppr, Pqr, Pps, Pqs);
}

// ---------------------------------------------------------------------------
// Direct conv, float4 over t, CO_BLK=8 output channels/thread (occupancy).
// Weights smem [tap][o] duplicated float2 -> broadcast LDS.128 pairs.
// Accumulation order per output identical to R1 (ci,kh,kw).
// ---------------------------------------------------------------------------
template<int CI, int CO, int CO_BLK, int K, int H, int W, int OH, int OW, int PAD>
__global__ __launch_bounds__(256)
void conv_kernel(const float* __restrict__ x, const float* __restrict__ wgt,
                 float* __restrict__ y) {
    constexpr int TAPS = CI * K * K;
    __shared__ float2 ws[TAPS * CO_BLK];
    const int oBase = blockIdx.y * CO_BLK;
    for (int i = threadIdx.x; i < TAPS * CO_BLK; i += blockDim.x) {
        int o = i % CO_BLK, tap = i / CO_BLK;
        float v = wgt[(oBase + o) * TAPS + tap];
        ws[i] = make_float2(v, v);
    }
    __syncthreads();

    long long g = (long long)blockIdx.x * blockDim.x + threadIdx.x;
    int tc = (int)(g % TC4); long long r = g / TC4;
    int ox = (int)(r % OW); r /= OW;
    int oy = (int)(r % OH); r /= OH;
    int n  = (int)r;
    if (n >= NBATCH) return;

    ulonglong2 acc[CO_BLK];
    #pragma unroll
    for (int o = 0; o < CO_BLK; o++) acc[o] = make_ulonglong2(0ULL, 0ULL);

    const float* xb = x + (size_t)n * CI * H * W * T_LEN + tc * 4;

    #pragma unroll 2
    for (int ci = 0; ci < CI; ci++) {
        #pragma unroll
        for (int kh = 0; kh < K; kh++) {
            int iy = oy + kh - PAD;
            if ((unsigned)iy >= (unsigned)H) continue;
            const float* xrow = xb + (size_t)(ci * H + iy) * W * T_LEN;
            #pragma unroll
            for (int kw = 0; kw < K; kw++) {
                int ix = ox + kw - PAD;
                if ((unsigned)ix >= (unsigned)W) continue;
                float4 f = *(const float4*)(xrow + (size_t)ix * T_LEN);
                ulonglong2 xu = *(ulonglong2*)&f;
                const float2* wrow = &ws[((ci * K + kh) * K + kw) * CO_BLK];
                #pragma unroll
                for (int o = 0; o < CO_BLK; o += 2) {
                    float4 wv = *(const float4*)(wrow + o);
                    ull w0 = ((ull*)&wv)[0];
                    ull w1 = ((ull*)&wv)[1];
                    acc[o].x   = ffma2(w0, xu.x, acc[o].x);
                    acc[o].y   = ffma2(w0, xu.y, acc[o].y);
                    acc[o+1].x = ffma2(w1, xu.x, acc[o+1].x);
                    acc[o+1].y = ffma2(w1, xu.y, acc[o+1].y);
                }
            }
        }
    }
    #pragma unroll
    for (int o = 0; o < CO_BLK; o++) {
        size_t off = (((size_t)(n * CO + oBase + o) * OH + oy) * OW + ox) * T_LEN
                     + tc * 4;
        *(ulonglong2*)(y + off) = acc[o];
    }
}

// ---------------------------------------------------------------------------
// Dense over (C,H,W)=3136 per timestep: [8,64,7,7,300] -> [8,10,300].
// ---------------------------------------------------------------------------
__global__ __launch_bounds__(256)
void dense_kernel(const float* __restrict__ x, const float* __restrict__ wgt,
                  float* __restrict__ y) {
    int g = blockIdx.x * blockDim.x + threadIdx.x;
    if (g >= NBATCH * 10 * T_LEN) return;
    int t = g % T_LEN; int r = g / T_LEN;
    int o = r % 10;    int n = r / 10;
    const float* xb = x + (size_t)n * 3136 * T_LEN + t;
    const float* wb = wgt + o * 3136;
    float acc = 0.f;
    #pragma unroll 8
    for (int i = 0; i < 3136; i++)
        acc = fmaf(wb[i], xb[(size_t)i * T_LEN], acc);
    y[g] = acc;
}

// ---------------------------------------------------------------------------

static inline int cdiv(long long a, long long b) { return (int)((a + b - 1) / b); }

extern "C" void kernel_launch(void* const* d_in, const int* in_sizes, int n_in,
                              void* d_out, int out_size) {
    const float* in = (const float*)d_in[0];   // [8,1,30,30,300]
    const float* w1 = (const float*)d_in[1];   // [16,1,5,5]
    const float* w2 = (const float*)d_in[2];   // [32,16,3,3]
    const float* w3 = (const float*)d_in[3];   // [64,32,3,3]
    const float* w4 = (const float*)d_in[4];   // [10,64,7,7]
    float* out = (float*)d_out;                // [8,10,300]

    float *bufA, *bufB;
    cudaGetSymbolAddress((void**)&bufA, g_bufA);
    cudaGetSymbolAddress((void**)&bufB, g_bufB);

    // P0 = psp(input)  [8,1,30,30,300]
    scan_t<0><<<cdiv(7200, 128), 128>>>(in, bufA, 7200);

    // u1 = conv1(P0)   [8,16,28,28,300]
    conv_kernel<1, 16, 8, 5, 30, 30, 28, 28, 1>
        <<<dim3(cdiv((long long)NBATCH * 28 * 28 * TC4, 256), 2), 256>>>(bufA, w1, bufB);

    // Q2 = psp(spike(pool(psp(spike(u1)))))  [8,16,14,14,300]
    scanpool2x<<<25088 / 128, 128>>>(bufB, bufA, 16, 14, 14);

    // u3 = conv2(Q2)   [8,32,14,14,300]
    conv_kernel<16, 32, 8, 3, 14, 14, 14, 14, 1>
        <<<dim3(cdiv((long long)NBATCH * 14 * 14 * TC4, 256), 4), 256>>>(bufA, w2, bufB);

    // Q4 = psp(spike(pool(psp(spike(u3)))))  [8,32,7,7,300]
    scanpool2x<<<12544 / 128, 128>>>(bufB, bufA, 32, 7, 7);

    // u5 = conv3(Q4)   [8,64,7,7,300]
    conv_kernel<32, 64, 8, 3, 7, 7, 7, 7, 1>
        <<<dim3(cdiv((long long)NBATCH * 7 * 7 * TC4, 256), 8), 256>>>(bufA, w3, bufB);

    // Q5 = psp(spike(u5))  [8,64,7,7,300]
    scan_t<1><<<cdiv(25088, 128), 128>>>(bufB, bufA, 25088);

    // u6 = dense(Q5)   [8,10,300]
    dense_kernel<<<cdiv(NBATCH * 10 * T_LEN, 256), 256>>>(bufA, w4, bufB);

    // out = spike(u6)
    scan_t<2><<<1, 128>>>(bufB, out, 80);
}